// round 13
// baseline (speedup 1.0000x reference)
#include <cuda_runtime.h>
#include <cuda_bf16.h>
#include <cuda_fp16.h>
#include <cstdint>

#define MM 512
#define NCOMBO 60
#define NCAT 7463
#define DH 512
#define RAWD 15360
#define NROWS (MM * NCOMBO)
#define NKT3 59
#define NPADB (NKT3 * 128)
#define LOG_SMEM 92160          /* 3 stages x 30720B (A 256x80 + B 128x80) */
#define RR1_SMEM 73728
#define RRSPLIT 8

__device__ __align__(16) float g_h[(size_t)NROWS * DH];
__device__ __align__(16) __half g_hf[(size_t)NROWS * DH];
__device__ __align__(16) __half g_wf[(size_t)NPADB * DH];
__device__ __align__(16) float g_wt[(size_t)NPADB * DH];
__device__ __align__(16) __nv_bfloat16 g_rawh[(size_t)MM * RAWD];
__device__ __align__(16) __nv_bfloat16 g_rawl[(size_t)MM * RAWD];
__device__ __align__(16) __nv_bfloat16 g_w1h[(size_t)MM * RAWD];
__device__ __align__(16) __nv_bfloat16 g_w1l[(size_t)MM * RAWD];
__device__ __align__(16) float g_part[RRSPLIT * MM * 512];
__device__ __align__(16) float g_rr1[MM * 512];
__device__ __align__(16) float g_rr2[MM * 256];
__device__ __align__(16) float g_rr3[MM * 127];
__device__ int   g_bh[MM];
__device__ float g_hsum[NROWS];
__device__ __align__(16) float g_t1v[(size_t)NROWS * 64];
__device__ __align__(16) float g_t2v[(size_t)NROWS * 64];
__device__ __align__(16) int   g_t1i[(size_t)NROWS * 64];
__device__ int g_wmax_i;

__constant__ int HP[6][2] = {{0,1},{0,2},{0,3},{1,2},{1,3},{2,3}};
__constant__ int BT[10][3] = {{4,5,6},{4,5,7},{4,5,8},{4,6,7},{4,6,8},
                              {4,7,8},{5,6,7},{5,6,8},{5,7,8},{6,7,8}};

__device__ __forceinline__ void mma16(float* d, const uint32_t* a, const uint32_t* b) {
    asm volatile("mma.sync.aligned.m16n8k16.row.col.f32.bf16.bf16.f32 "
                 "{%0,%1,%2,%3}, {%4,%5,%6,%7}, {%8,%9}, {%0,%1,%2,%3};"
                 : "+f"(d[0]), "+f"(d[1]), "+f"(d[2]), "+f"(d[3])
                 : "r"(a[0]), "r"(a[1]), "r"(a[2]), "r"(a[3]), "r"(b[0]), "r"(b[1]));
}
__device__ __forceinline__ void mma16h(float* d, const uint32_t* a, const uint32_t* b) {
    asm volatile("mma.sync.aligned.m16n8k16.row.col.f32.f16.f16.f32 "
                 "{%0,%1,%2,%3}, {%4,%5,%6,%7}, {%8,%9}, {%0,%1,%2,%3};"
                 : "+f"(d[0]), "+f"(d[1]), "+f"(d[2]), "+f"(d[3])
                 : "r"(a[0]), "r"(a[1]), "r"(a[2]), "r"(a[3]), "r"(b[0]), "r"(b[1]));
}
__device__ __forceinline__ void ldsm4(uint32_t* r, uint32_t addr) {
    asm volatile("ldmatrix.sync.aligned.m8n8.x4.shared.b16 {%0,%1,%2,%3}, [%4];"
                 : "=r"(r[0]), "=r"(r[1]), "=r"(r[2]), "=r"(r[3]) : "r"(addr));
}
__device__ __forceinline__ void ldsm2(uint32_t* r, uint32_t addr) {
    asm volatile("ldmatrix.sync.aligned.m8n8.x2.shared.b16 {%0,%1}, [%2];"
                 : "=r"(r[0]), "=r"(r[1]) : "r"(addr));
}
__device__ __forceinline__ void cpa16(uint32_t dst, const void* src) {
    asm volatile("cp.async.ca.shared.global [%0], [%1], 16;" :: "r"(dst), "l"(src));
}
#define CP_COMMIT() asm volatile("cp.async.commit_group;" ::: "memory")
#define CP_WAIT1()  asm volatile("cp.async.wait_group 1;" ::: "memory")
#define CP_WAIT0()  asm volatile("cp.async.wait_group 0;" ::: "memory")

__global__ void k_init() {
    int i = blockIdx.x * blockDim.x + threadIdx.x;
    if (i == 0) g_wmax_i = 0;
    if (i < MM) g_bh[i] = 0x7fffffff;
}

__global__ __launch_bounds__(256) void k_packWb(const float* __restrict__ W) {
    __shared__ float t[32][33];
    const int tid = threadIdx.x, tx = tid & 31, ty = tid >> 5;
    const int n0 = blockIdx.x * 32, k0 = blockIdx.y * 32;
    float lm = 0.f;
    #pragma unroll
    for (int i = 0; i < 4; i++) {
        int k = k0 + ty + i * 8, n = n0 + tx;
        float w = (n < NCAT) ? W[(size_t)k * NCAT + n] : 0.f;
        t[ty + i * 8][tx] = w;
        lm = fmaxf(lm, fabsf(w));
    }
    __syncthreads();
    #pragma unroll
    for (int i = 0; i < 4; i++) {
        int nl = ty + i * 8;
        float v = t[tx][nl];
        g_wf[(size_t)(n0 + nl) * 512 + k0 + tx] = __float2half_rn(v);
        g_wt[(size_t)(n0 + nl) * 512 + k0 + tx] = v;
    }
    #pragma unroll
    for (int d = 16; d; d >>= 1) lm = fmaxf(lm, __shfl_xor_sync(0xffffffffu, lm, d));
    if ((tid & 31) == 0) atomicMax(&g_wmax_i, __float_as_int(lm));
}

__global__ __launch_bounds__(256) void k_packW1(const float* __restrict__ W) {
    __shared__ float t[32][33];
    const int tid = threadIdx.x, tx = tid & 31, ty = tid >> 5;
    const int n0 = blockIdx.x * 32, k0 = blockIdx.y * 32;
    #pragma unroll
    for (int i = 0; i < 4; i++)
        t[ty + i * 8][tx] = W[(size_t)(k0 + ty + i * 8) * 512 + n0 + tx];
    __syncthreads();
    #pragma unroll
    for (int i = 0; i < 4; i++) {
        int nl = ty + i * 8;
        float v = t[tx][nl];
        __nv_bfloat16 hi = __float2bfloat16(v);
        g_w1h[(size_t)(n0 + nl) * RAWD + k0 + tx] = hi;
        g_w1l[(size_t)(n0 + nl) * RAWD + k0 + tx] = __float2bfloat16(v - __bfloat162float(hi));
    }
}

__global__ __launch_bounds__(256) void k_features(
    const int* __restrict__ x,
    const float* __restrict__ w_suit, const float* __restrict__ b_suit,
    const float* __restrict__ g_suit, const float* __restrict__ be_suit,
    const float* __restrict__ w_rank, const float* __restrict__ b_rank,
    const float* __restrict__ g_rank, const float* __restrict__ be_rank,
    const float* __restrict__ w_h1, const float* __restrict__ b_h1,
    const float* __restrict__ w_h2, const float* __restrict__ b_h2)
{
    __shared__ float s_wr[400], s_ws[80], s_w1[512], s_w2[1024];
    __shared__ float s_b1[32], s_b2[32];
    __shared__ float s_br[16], s_gr[16], s_ber[16], s_bs[16], s_gs[16], s_bes[16];
    __shared__ int s_rank[9], s_suit[9];
    __shared__ float p_sr[960], p_qr[960], p_ss[960], p_qs[960];
    __shared__ float mu_r[16], si_r[16], mu_s[16], si_s[16];

    const int m = blockIdx.x, tid = threadIdx.x;
    for (int i = tid; i < 400; i += 256) s_wr[i] = w_rank[i];
    for (int i = tid; i < 80;  i += 256) s_ws[i] = w_suit[i];
    for (int i = tid; i < 512; i += 256) s_w1[i] = w_h1[i];
    for (int i = tid; i < 1024; i += 256) s_w2[i] = w_h2[i];
    if (tid < 32) { s_b1[tid] = b_h1[tid]; s_b2[tid] = b_h2[tid]; }
    if (tid < 16) {
        s_br[tid] = b_rank[tid]; s_gr[tid] = g_rank[tid]; s_ber[tid] = be_rank[tid];
        s_bs[tid] = b_suit[tid]; s_gs[tid] = g_suit[tid]; s_bes[tid] = be_suit[tid];
    }
    if (tid == 0) {
        int key[9];
        for (int j = 0; j < 9; j++) {
            int r = x[m * 18 + 2 * j], s = x[m * 18 + 2 * j + 1];
            key[j] = (r << 8) | (s << 4) | j;
        }
        for (int seg = 0; seg < 2; seg++) {
            int lo = seg ? 4 : 0, hi = seg ? 9 : 4;
            for (int a = lo + 1; a < hi; a++) {
                int v = key[a]; int b = a - 1;
                while (b >= lo && key[b] > v) { key[b + 1] = key[b]; b--; }
                key[b + 1] = v;
            }
        }
        for (int j = 0; j < 9; j++) { s_rank[j] = key[j] >> 8; s_suit[j] = (key[j] >> 4) & 15; }
    }
    __syncthreads();

    for (int t = tid; t < 960; t += 256) {
        int n = t >> 4, o = t & 15;
        const int* hp = HP[n / 10];
        const int* bt = BT[n % 10];
        int rk[5] = {s_rank[hp[0]], s_rank[hp[1]], s_rank[bt[0]], s_rank[bt[1]], s_rank[bt[2]]};
        int su[5] = {s_suit[hp[0]], s_suit[hp[1]], s_suit[bt[0]], s_suit[bt[1]], s_suit[bt[2]]};
        float br = s_br[o];
        float lsum = 6.f * br, lsq = 6.f * br * br;
        #pragma unroll
        for (int tt = 0; tt < 5; tt++) {
            float v = br;
            #pragma unroll
            for (int c = 0; c < 5; c++) { int d = rk[c] - tt; if (d >= 0) v += s_wr[o * 25 + c * 5 + d]; }
            lsum += v; lsq += v * v;
        }
        p_sr[t] = lsum; p_qr[t] = lsq;
        float bs = s_bs[o];
        float l2 = 0.f, q2 = 0.f;
        #pragma unroll
        for (int l = 0; l < 5; l++) {
            float v = bs;
            #pragma unroll
            for (int c = 0; c < 5; c++) if (su[c] == l) v += s_ws[o * 5 + c];
            l2 += v; q2 += v * v;
        }
        p_ss[t] = l2; p_qs[t] = q2;
    }
    __syncthreads();
    if (tid < 16) {
        float s = 0.f, q = 0.f;
        for (int n = 0; n < 60; n++) { s += p_sr[n * 16 + tid]; q += p_qr[n * 16 + tid]; }
        float mu = s / 660.f, var = q / 660.f - mu * mu;
        mu_r[tid] = mu; si_r[tid] = rsqrtf(var + 1e-5f) * s_gr[tid];
        s = 0.f; q = 0.f;
        for (int n = 0; n < 60; n++) { s += p_ss[n * 16 + tid]; q += p_qs[n * 16 + tid]; }
        mu = s / 300.f; var = q / 300.f - mu * mu;
        mu_s[tid] = mu; si_s[tid] = rsqrtf(var + 1e-5f) * s_gs[tid];
    }
    __syncthreads();

    for (int t = tid; t < 960; t += 256) {
        int n = t >> 4, o = t & 15;
        const int* hp = HP[n / 10];
        const int* bt = BT[n % 10];
        int rk[5] = {s_rank[hp[0]], s_rank[hp[1]], s_rank[bt[0]], s_rank[bt[1]], s_rank[bt[2]]};
        int su[5] = {s_suit[hp[0]], s_suit[hp[1]], s_suit[bt[0]], s_suit[bt[1]], s_suit[bt[2]]};
        float out16[16];
        float br = s_br[o], mr = mu_r[o], sr = si_r[o], er = s_ber[o];
        #pragma unroll
        for (int tt = 0; tt < 5; tt++) {
            float v = br;
            #pragma unroll
            for (int c = 0; c < 5; c++) { int d = rk[c] - tt; if (d >= 0) v += s_wr[o * 25 + c * 5 + d]; }
            out16[tt] = fmaxf((v - mr) * sr + er, 0.f);
        }
        float z = fmaxf((br - mr) * sr + er, 0.f);
        #pragma unroll
        for (int tt = 5; tt < 11; tt++) out16[tt] = z;
        float bs = s_bs[o], ms = mu_s[o], ss = si_s[o], es = s_bes[o];
        #pragma unroll
        for (int l = 0; l < 5; l++) {
            float v = bs;
            #pragma unroll
            for (int c = 0; c < 5; c++) if (su[c] == l) v += s_ws[o * 5 + c];
            out16[11 + l] = fmaxf((v - ms) * ss + es, 0.f);
        }
        size_t rbase = (size_t)m * RAWD + n * 256 + o * 16;
        #pragma unroll
        for (int i = 0; i < 16; i++) {
            float a = out16[i];
            __nv_bfloat16 hi = __float2bfloat16(a);
            g_rawh[rbase + i] = hi;
            g_rawl[rbase + i] = __float2bfloat16(a - __bfloat162float(hi));
        }
        float h1[32];
        #pragma unroll
        for (int p = 0; p < 32; p++) {
            float a = s_b1[p];
            #pragma unroll
            for (int i = 0; i < 16; i++) a += out16[i] * s_w1[i * 32 + p];
            h1[p] = fmaxf(a, 0.f);
        }
        size_t hbase = ((size_t)(m * 60 + n)) * DH + o * 32;
        float hs = 0.f;
        #pragma unroll
        for (int q = 0; q < 32; q++) {
            float a = s_b2[q];
            #pragma unroll
            for (int p = 0; p < 32; p++) a += h1[p] * s_w2[p * 32 + q];
            a = fmaxf(a, 0.f);
            g_h[hbase + q] = a;
            g_hf[hbase + q] = __float2half_rn(a);
            hs += a;
        }
        hs += __shfl_xor_sync(0xffffffffu, hs, 1);
        hs += __shfl_xor_sync(0xffffffffu, hs, 2);
        hs += __shfl_xor_sync(0xffffffffu, hs, 4);
        hs += __shfl_xor_sync(0xffffffffu, hs, 8);
        if (o == 0) g_hsum[m * 60 + n] = hs;
    }
}

// ---- single-term fp16 tensor GEMM, 256x128 CTA tile, 512 thr, cp.async 3-stage ----
__global__ __launch_bounds__(512, 1) void k_logits_bf(const float* __restrict__ bcat)
{
    extern __shared__ uint32_t su[];
    const int tid = threadIdx.x, lane = tid & 31, wid = tid >> 5;
    const int wm = wid & 3, wn = wid >> 2;       // wm: 4x64 M, wn: 4x32 N
    const int g = lane >> 2, tg = lane & 3;
    const int row0 = blockIdx.x * 256, col0 = blockIdx.y * 128;
    const uint32_t sbase = (uint32_t)__cvta_generic_to_shared(su);

    float acc[4][4][4];
    #pragma unroll
    for (int mi = 0; mi < 4; mi++)
        #pragma unroll
        for (int nf = 0; nf < 4; nf++)
            #pragma unroll
            for (int c = 0; c < 4; c++) acc[mi][nf][c] = 0.f;

    auto issue = [&](int stg, int s) {
        const int k0 = s * 32;
        const uint32_t sb = sbase + stg * 30720;
        #pragma unroll
        for (int i = 0; i < 2; i++) {
            int c = tid + i * 512;              // 0..1023
            int mr = c >> 2, q = c & 3;
            cpa16(sb + (uint32_t)(mr * 80 + q * 16),
                  g_hf + (size_t)(row0 + mr) * 512 + k0 + q * 8);
        }
        {
            int nr = tid >> 2, q = tid & 3;     // 512 ops
            cpa16(sb + 20480u + (uint32_t)(nr * 80 + q * 16),
                  g_wf + (size_t)(col0 + nr) * 512 + k0 + q * 8);
        }
        CP_COMMIT();
    };

    const int a_rl = lane & 15;
    const int a_k4 = (lane >> 4) * 4;
    const int b_rl = lane & 7;
    const int b_k4 = ((lane >> 3) & 1) * 4;

    auto compute = [&](int stg) {
        const uint32_t sb = sbase + stg * 30720;
        #pragma unroll
        for (int kq = 0; kq < 16; kq += 8) {
            uint32_t ah[4][4], bf[4][2];
            #pragma unroll
            for (int mi = 0; mi < 4; mi++) {
                int row = wm * 64 + mi * 16 + a_rl;
                ldsm4(ah[mi], sb + (uint32_t)((row * 20 + kq + a_k4) * 4));
            }
            #pragma unroll
            for (int nf = 0; nf < 4; nf++) {
                int row = wn * 32 + nf * 8 + b_rl;
                ldsm2(bf[nf], sb + 20480u + (uint32_t)((row * 20 + kq + b_k4) * 4));
            }
            #pragma unroll
            for (int mi = 0; mi < 4; mi++)
                #pragma unroll
                for (int nf = 0; nf < 4; nf++)
                    mma16h(acc[mi][nf], ah[mi], bf[nf]);
        }
    };

    issue(0, 0);
    issue(1, 1);
    #pragma unroll 1
    for (int s = 0; s < 16; s++) {
        if (s < 14) { CP_WAIT1(); } else { CP_WAIT0(); }
        __syncthreads();
        compute(s % 3);
        if (s + 2 < 16) issue((s + 2) % 3, s + 2);
    }
    __syncthreads();

    float* e_v1 = (float*)su;             // [256][4]
    float* e_v2 = (float*)(su + 1024);
    int*   e_i1 = (int*)(su + 2048);

    float tv1[8], tv2[8]; int ti1[8];
    #pragma unroll
    for (int q = 0; q < 8; q++) { tv1[q] = -3.0e38f; tv2[q] = -3.0e38f; ti1[q] = 0; }
    #pragma unroll
    for (int nf = 0; nf < 4; nf++) {
        #pragma unroll
        for (int j = 0; j < 2; j++) {
            int gc = col0 + wn * 32 + nf * 8 + tg * 2 + j;
            float bj = (gc < NCAT) ? __ldg(&bcat[gc]) : 0.f;
            #pragma unroll
            for (int mi = 0; mi < 4; mi++)
                #pragma unroll
                for (int hf = 0; hf < 2; hf++) {
                    int q = mi * 2 + hf;
                    float v = (gc < NCAT) ? acc[mi][nf][hf * 2 + j] + bj : -3.0e38f;
                    if (v > tv1[q]) { tv2[q] = tv1[q]; tv1[q] = v; ti1[q] = gc; }
                    else if (v > tv2[q]) tv2[q] = v;
                }
        }
    }
    #pragma unroll
    for (int q = 0; q < 8; q++) {
        float v1 = tv1[q], v2 = tv2[q]; int i1 = ti1[q];
        #pragma unroll
        for (int d = 1; d <= 2; d <<= 1) {
            float ov1 = __shfl_xor_sync(0xffffffffu, v1, d);
            int   oi1 = __shfl_xor_sync(0xffffffffu, i1, d);
            float ov2 = __shfl_xor_sync(0xffffffffu, v2, d);
            if (ov1 > v1)      { v2 = fmaxf(v1, ov2); v1 = ov1; i1 = oi1; }
            else if (ov1 < v1) { v2 = fmaxf(v2, ov1); }
            else               { i1 = min(i1, oi1); v2 = v1; }
        }
        if (tg == 0) {
            int mi = q >> 1, hf = q & 1;
            int lr = wm * 64 + mi * 16 + hf * 8 + g;
            e_v1[lr * 4 + wn] = v1; e_v2[lr * 4 + wn] = v2; e_i1[lr * 4 + wn] = i1;
        }
    }
    __syncthreads();
    if (tid < 256) {
        float v1 = e_v1[tid * 4], v2 = e_v2[tid * 4]; int i1 = e_i1[tid * 4];
        #pragma unroll
        for (int t = 1; t < 4; t++) {
            float ov1 = e_v1[tid * 4 + t], ov2 = e_v2[tid * 4 + t]; int oi1 = e_i1[tid * 4 + t];
            if (ov1 > v1)      { v2 = fmaxf(v1, ov2); v1 = ov1; i1 = oi1; }
            else if (ov1 < v1) { v2 = fmaxf(v2, ov1); }
            else               { i1 = min(i1, oi1); v2 = v1; }
        }
        size_t o = (size_t)(row0 + tid) * 64 + blockIdx.y;
        g_t1v[o] = v1; g_t2v[o] = v2; g_t1i[o] = i1;
    }
}

__global__ __launch_bounds__(128) void k_argmax(const float* __restrict__ bcat)
{
    const int row = blockIdx.x, tid = threadIdx.x;
    __shared__ float sh[512];
    __shared__ float s_tv[64], s_t2[64];
    __shared__ int   s_ti[64];
    __shared__ int   s_single[64], s_tiles[64];
    __shared__ int   s_ns, s_nt;
    __shared__ float rbv[128];
    __shared__ int   rbi[128];

    const float* hrow = &g_h[(size_t)row * DH];
    for (int i = tid; i < 512; i += 128) sh[i] = hrow[i];
    if (tid < 64) {
        bool valid = tid < NKT3;
        size_t o = (size_t)row * 64 + tid;
        s_tv[tid] = valid ? g_t1v[o] : -3.0e38f;
        s_t2[tid] = valid ? g_t2v[o] : -3.0e38f;
        s_ti[tid] = valid ? g_t1i[o] : 0;
    }
    __syncthreads();
    if (tid == 0) {
        float gmax = -3.0e38f;
        for (int t = 0; t < NKT3; t++) gmax = fmaxf(gmax, s_tv[t]);
        float wmax = __int_as_float(g_wmax_i);
        float thr = gmax - wmax * g_hsum[row] * 0.001953125f;   // 2^-9 margin
        int ns = 0, nt = 0;
        for (int t = 0; t < NKT3; t++) {
            if (s_tv[t] >= thr) {
                if (s_t2[t] >= thr) s_tiles[nt++] = t;
                else                s_single[ns++] = s_ti[t];
            }
        }
        s_ns = ns; s_nt = nt;
    }
    __syncthreads();

    const int total = s_ns + s_nt * 128;
    float bv = -3.0e38f; int bi = 0x7fffffff;
    for (int e = tid; e < total; e += 128) {
        int col;
        if (e < s_ns) col = s_single[e];
        else { int r = e - s_ns; col = s_tiles[r >> 7] * 128 + (r & 127); }
        if (col < NCAT) {
            float a = bcat[col];
            const float4* wc4 = (const float4*)(g_wt + (size_t)col * 512);
            #pragma unroll 4
            for (int k = 0; k < 128; k++) {
                float4 w = wc4[k];
                a = fmaf(sh[k * 4 + 0], w.x, a);
                a = fmaf(sh[k * 4 + 1], w.y, a);
                a = fmaf(sh[k * 4 + 2], w.z, a);
                a = fmaf(sh[k * 4 + 3], w.w, a);
            }
            if (a > bv || (a == bv && col < bi)) { bv = a; bi = col; }
        }
    }
    rbv[tid] = bv; rbi[tid] = bi;
    __syncthreads();
    if (tid == 0) {
        for (int t = 1; t < 128; t++)
            if (rbv[t] > bv || (rbv[t] == bv && rbi[t] < bi)) { bv = rbv[t]; bi = rbi[t]; }
        atomicMin(&g_bh[row / 60], bi);
    }
}

// ---- rr1: 3-term split-bf16 tensor GEMM (R9-proven) ----
__global__ __launch_bounds__(256, 2) void k_rr1t()
{
    extern __shared__ uint32_t su[];
    const int tid = threadIdx.x, lane = tid & 31, wid = tid >> 5;
    const int wm = wid & 3, wn = wid >> 2;
    const int g = lane >> 2, tg = lane & 3;
    const int row0 = blockIdx.y * 128, col0 = blockIdx.x * 128;
    const int kb = blockIdx.z * (RAWD / RRSPLIT);
    const int NSTEPS = (RAWD / RRSPLIT) / 16;
    const uint32_t sbase = (uint32_t)__cvta_generic_to_shared(su);

    float acc[2][8][4];
    #pragma unroll
    for (int mi = 0; mi < 2; mi++)
        #pragma unroll
        for (int nf = 0; nf < 8; nf++)
            #pragma unroll
            for (int c = 0; c < 4; c++) acc[mi][nf][c] = 0.f;

    const int r = tid >> 1, q = tid & 1;
    auto issue = [&](int stg, int s) {
        const int k0 = kb + s * 16;
        const uint32_t sb = sbase + stg * 24576 + (uint32_t)(r * 48 + q * 16);
        size_t ao = (size_t)(row0 + r) * RAWD + k0 + q * 8;
        size_t bo = (size_t)(col0 + r) * RAWD + k0 + q * 8;
        cpa16(sb,          g_rawh + ao);
        cpa16(sb + 6144u,  g_rawl + ao);
        cpa16(sb + 12288u, g_w1h + bo);
        cpa16(sb + 18432u, g_w1l + bo);
        CP_COMMIT();
    };

    auto compute = [&](int stg) {
        const uint32_t* Ah = su + stg * 6144;
        const uint32_t* Al = Ah + 1536;
        const uint32_t* Bh = Ah + 3072;
        const uint32_t* Bl = Ah + 4608;
        uint32_t ah[2][4], al[2][4], bh[8][2], bl[8][2];
        #pragma unroll
        for (int mi = 0; mi < 2; mi++) {
            int m0 = (wm * 32 + mi * 16 + g) * 12 + tg;
            ah[mi][0] = Ah[m0];     ah[mi][1] = Ah[m0 + 96];
            ah[mi][2] = Ah[m0 + 4]; ah[mi][3] = Ah[m0 + 100];
            al[mi][0] = Al[m0];     al[mi][1] = Al[m0 + 96];
            al[mi][2] = Al[m0 + 4]; al[mi][3] = Al[m0 + 100];
        }
        #pragma unroll
        for (int nf = 0; nf < 8; nf++) {
            int n0 = (wn * 64 + nf * 8 + g) * 12 + tg;
            bh[nf][0] = Bh[n0]; bh[nf][1] = Bh[n0 + 4];
            bl[nf][0] = Bl[n0]; bl[nf][1] = Bl[n0 + 4];
        }
        #pragma unroll
        for (int mi = 0; mi < 2; mi++)
            #pragma unroll
            for (int nf = 0; nf < 8; nf++) {
                mma16(acc[mi][nf], ah[mi], bh[nf]);
                mma16(acc[mi][nf], al[mi], bh[nf]);
                mma16(acc[mi][nf], ah[mi], bl[nf]);
            }
    };

    issue(0, 0);
    issue(1, 1);
    #pragma unroll 1
    for (int s = 0; s < NSTEPS; s++) {
        if (s < NSTEPS - 2) { CP_WAIT1(); } else { CP_WAIT0(); }
        __syncthreads();
        compute(s % 3);
        if (s + 2 < NSTEPS) issue((s + 2) % 3, s + 2);
        __syncthreads();
    }

    #pragma unroll
    for (int mi = 0; mi < 2; mi++)
        #pragma unroll
        for (int nf = 0; nf < 8; nf++)
            #pragma unroll
            for (int c = 0; c < 4; c++) {
                int grow = row0 + wm * 32 + mi * 16 + (c >> 1) * 8 + g;
                int gcol = col0 + wn * 64 + nf * 8 + tg * 2 + (c & 1);
                g_part[((size_t)blockIdx.z * MM + grow) * 512 + gcol] = acc[mi][nf][c];
            }
}

__global__ __launch_bounds__(256) void k_rr1red(const float* __restrict__ b)
{
    int m = blockIdx.x;
    for (int c = threadIdx.x; c < 512; c += 256) {
        float s = 0.f;
        #pragma unroll
        for (int z = 0; z < RRSPLIT; z++)
            s += g_part[((size_t)z * MM + m) * 512 + c];
        g_rr1[m * 512 + c] = fmaxf(s + b[c], 0.f);
    }
}

__global__ __launch_bounds__(256) void k_rr2(const float* __restrict__ W, const float* __restrict__ b)
{
    __shared__ float arow[512];
    int m = blockIdx.x, tid = threadIdx.x;
    for (int i = tid; i < 512; i += 256) arow[i] = g_rr1[m * 512 + i];
    __syncthreads();
    float a = b[tid];
    for (int k = 0; k < 512; k++) a += arow[k] * W[k * 256 + tid];
    g_rr2[m * 256 + tid] = fmaxf(a, 0.f);
}

__global__ __launch_bounds__(128) void k_rr3(const float* __restrict__ W, const float* __restrict__ b)
{
    __shared__ float arow[256];
    int m = blockIdx.x, tid = threadIdx.x;
    for (int i = tid; i < 256; i += 128) arow[i] = g_rr2[m * 256 + i];
    __syncthreads();
    if (tid < 127) {
        float a = b[tid];
        for (int k = 0; k < 256; k++) a += arow[k] * W[k * 127 + tid];
        g_rr3[m * 127 + tid] = fmaxf(a, 0.f);
    }
}

__global__ __launch_bounds__(32) void k_final(const float* __restrict__ w_sc,
                                              const float* __restrict__ b_sc,
                                              float* __restrict__ out)
{
    __shared__ float row[127];
    int m = blockIdx.x, tid = threadIdx.x;
    for (int i = tid; i < 127; i += 32) row[i] = g_rr3[m * 127 + i];
    __syncwarp();
    if (tid < 6) {
        float s = b_sc[tid];
        for (int k = 0; k < 127; k++) s += row[k] * w_sc[k * 6 + tid];
        s += (float)g_bh[m] * w_sc[127 * 6 + tid];
        out[m * 6 + tid] = s;
    }
}

extern "C" void kernel_launch(void* const* d_in, const int* in_sizes, int n_in,
                              void* d_out, int out_size)
{
    const int*   x      = (const int*)d_in[0];
    const float* w_suit = (const float*)d_in[1];
    const float* b_suit = (const float*)d_in[2];
    const float* gg_s   = (const float*)d_in[3];
    const float* be_s   = (const float*)d_in[4];
    const float* w_rank = (const float*)d_in[5];
    const float* b_rank = (const float*)d_in[6];
    const float* gg_r   = (const float*)d_in[7];
    const float* be_r   = (const float*)d_in[8];
    const float* w_h1   = (const float*)d_in[9];
    const float* b_h1   = (const float*)d_in[10];
    const float* w_h2   = (const float*)d_in[11];
    const float* b_h2   = (const float*)d_in[12];
    const float* w_cat  = (const float*)d_in[13];
    const float* b_cat  = (const float*)d_in[14];
    const float* w_o1   = (const float*)d_in[15];
    const float* b_o1   = (const float*)d_in[16];
    const float* w_o2   = (const float*)d_in[17];
    const float* b_o2   = (const float*)d_in[18];
    const float* w_o3   = (const float*)d_in[19];
    const float* b_o3   = (const float*)d_in[20];
    const float* w_sc   = (const float*)d_in[21];
    const float* b_sc   = (const float*)d_in[22];
    float* out = (float*)d_out;

    static cudaStream_t s1 = nullptr;
    static cudaEvent_t evS = nullptr, evF = nullptr, evJ = nullptr, evP = nullptr;
    if (!s1) {
        cudaStreamCreateWithFlags(&s1, cudaStreamNonBlocking);
        cudaEventCreateWithFlags(&evS, cudaEventDisableTiming);
        cudaEventCreateWithFlags(&evF, cudaEventDisableTiming);
        cudaEventCreateWithFlags(&evJ, cudaEventDisableTiming);
        cudaEventCreateWithFlags(&evP, cudaEventDisableTiming);
        cudaFuncSetAttribute(k_logits_bf, cudaFuncAttributeMaxDynamicSharedMemorySize, LOG_SMEM);
        cudaFuncSetAttribute(k_rr1t, cudaFuncAttributeMaxDynamicSharedMemorySize, RR1_SMEM);
    }

    k_init<<<2, 256>>>();
    cudaEventRecord(evS, 0);
    cudaStreamWaitEvent(s1, evS, 0);

    dim3 gpw(NPADB / 32, 16);
    k_packWb<<<gpw, 256, 0, s1>>>(w_cat);
    cudaEventRecord(evP, s1);
    dim3 gp1(16, RAWD / 32);
    k_packW1<<<gp1, 256, 0, s1>>>(w_o1);

    k_features<<<MM, 256>>>(x, w_suit, b_suit, gg_s, be_s,
                            w_rank, b_rank, gg_r, be_r,
                            w_h1, b_h1, w_h2, b_h2);
    cudaEventRecord(evF, 0);
    cudaStreamWaitEvent(s1, evF, 0);

    dim3 g41(4, 4, RRSPLIT);
    k_rr1t<<<g41, 256, RR1_SMEM, s1>>>();
    k_rr1red<<<MM, 256, 0, s1>>>(b_o1);
    k_rr2<<<MM, 256, 0, s1>>>(w_o2, b_o2);
    k_rr3<<<MM, 128, 0, s1>>>(w_o3, b_o3);
    cudaEventRecord(evJ, s1);

    cudaStreamWaitEvent(0, evP, 0);
    dim3 gl(NROWS / 256, NKT3);
    k_logits_bf<<<gl, 512, LOG_SMEM>>>(b_cat);
    k_argmax<<<NROWS, 128>>>(b_cat);

    cudaStreamWaitEvent(0, evJ, 0);
    k_final<<<MM, 32>>>(w_sc, b_sc, out);
}

// round 14
// speedup vs baseline: 1.0865x; 1.0865x over previous
#include <cuda_runtime.h>
#include <cuda_bf16.h>
#include <cuda_fp16.h>
#include <cstdint>

#define MM 512
#define NCOMBO 60
#define NCAT 7463
#define DH 512
#define RAWD 15360
#define NROWS (MM * NCOMBO)
#define NKT3 59
#define NPADB (NKT3 * 128)
#define LOG_SMEM 81920          /* 4 stages x 20480B */
#define RR1_SMEM 73728
#define RRSPLIT 8

__device__ __align__(16) float g_h[(size_t)NROWS * DH];
__device__ __align__(16) __half g_hf[(size_t)NROWS * DH];
__device__ __align__(16) __half g_wf[(size_t)NPADB * DH];
__device__ __align__(16) float g_wt[(size_t)NPADB * DH];
__device__ __align__(16) __nv_bfloat16 g_rawh[(size_t)MM * RAWD];
__device__ __align__(16) __nv_bfloat16 g_rawl[(size_t)MM * RAWD];
__device__ __align__(16) __nv_bfloat16 g_w1h[(size_t)MM * RAWD];
__device__ __align__(16) __nv_bfloat16 g_w1l[(size_t)MM * RAWD];
__device__ __align__(16) float g_part[RRSPLIT * MM * 512];
__device__ __align__(16) float g_rr1[MM * 512];
__device__ __align__(16) float g_rr2[MM * 256];
__device__ __align__(16) float g_rr3[MM * 127];
__device__ int   g_bh[MM];
__device__ float g_hsum[NROWS];
__device__ __align__(16) float g_t1v[(size_t)NROWS * 64];
__device__ __align__(16) float g_t2v[(size_t)NROWS * 64];
__device__ __align__(16) int   g_t1i[(size_t)NROWS * 64];
__device__ int g_wmax_i;

__constant__ int HP[6][2] = {{0,1},{0,2},{0,3},{1,2},{1,3},{2,3}};
__constant__ int BT[10][3] = {{4,5,6},{4,5,7},{4,5,8},{4,6,7},{4,6,8},
                              {4,7,8},{5,6,7},{5,6,8},{5,7,8},{6,7,8}};

__device__ __forceinline__ void mma16(float* d, const uint32_t* a, const uint32_t* b) {
    asm volatile("mma.sync.aligned.m16n8k16.row.col.f32.bf16.bf16.f32 "
                 "{%0,%1,%2,%3}, {%4,%5,%6,%7}, {%8,%9}, {%0,%1,%2,%3};"
                 : "+f"(d[0]), "+f"(d[1]), "+f"(d[2]), "+f"(d[3])
                 : "r"(a[0]), "r"(a[1]), "r"(a[2]), "r"(a[3]), "r"(b[0]), "r"(b[1]));
}
__device__ __forceinline__ void mma16h(float* d, const uint32_t* a, const uint32_t* b) {
    asm volatile("mma.sync.aligned.m16n8k16.row.col.f32.f16.f16.f32 "
                 "{%0,%1,%2,%3}, {%4,%5,%6,%7}, {%8,%9}, {%0,%1,%2,%3};"
                 : "+f"(d[0]), "+f"(d[1]), "+f"(d[2]), "+f"(d[3])
                 : "r"(a[0]), "r"(a[1]), "r"(a[2]), "r"(a[3]), "r"(b[0]), "r"(b[1]));
}
__device__ __forceinline__ void ldsm4(uint32_t* r, uint32_t addr) {
    asm volatile("ldmatrix.sync.aligned.m8n8.x4.shared.b16 {%0,%1,%2,%3}, [%4];"
                 : "=r"(r[0]), "=r"(r[1]), "=r"(r[2]), "=r"(r[3]) : "r"(addr));
}
__device__ __forceinline__ void ldsm2(uint32_t* r, uint32_t addr) {
    asm volatile("ldmatrix.sync.aligned.m8n8.x2.shared.b16 {%0,%1}, [%2];"
                 : "=r"(r[0]), "=r"(r[1]) : "r"(addr));
}
__device__ __forceinline__ void cpa16(uint32_t dst, const void* src) {
    asm volatile("cp.async.ca.shared.global [%0], [%1], 16;" :: "r"(dst), "l"(src));
}
#define CP_COMMIT() asm volatile("cp.async.commit_group;" ::: "memory")
#define CP_WAIT2()  asm volatile("cp.async.wait_group 2;" ::: "memory")
#define CP_WAIT1()  asm volatile("cp.async.wait_group 1;" ::: "memory")
#define CP_WAIT0()  asm volatile("cp.async.wait_group 0;" ::: "memory")

__global__ void k_init() {
    int i = blockIdx.x * blockDim.x + threadIdx.x;
    if (i == 0) g_wmax_i = 0;
    if (i < MM) g_bh[i] = 0x7fffffff;
}

__global__ __launch_bounds__(256) void k_packWb(const float* __restrict__ W) {
    __shared__ float t[32][33];
    const int tid = threadIdx.x, tx = tid & 31, ty = tid >> 5;
    const int n0 = blockIdx.x * 32, k0 = blockIdx.y * 32;
    float lm = 0.f;
    #pragma unroll
    for (int i = 0; i < 4; i++) {
        int k = k0 + ty + i * 8, n = n0 + tx;
        float w = (n < NCAT) ? W[(size_t)k * NCAT + n] : 0.f;
        t[ty + i * 8][tx] = w;
        lm = fmaxf(lm, fabsf(w));
    }
    __syncthreads();
    #pragma unroll
    for (int i = 0; i < 4; i++) {
        int nl = ty + i * 8;
        float v = t[tx][nl];
        g_wf[(size_t)(n0 + nl) * 512 + k0 + tx] = __float2half_rn(v);
        g_wt[(size_t)(n0 + nl) * 512 + k0 + tx] = v;
    }
    #pragma unroll
    for (int d = 16; d; d >>= 1) lm = fmaxf(lm, __shfl_xor_sync(0xffffffffu, lm, d));
    if ((tid & 31) == 0) atomicMax(&g_wmax_i, __float_as_int(lm));
}

__global__ __launch_bounds__(256) void k_packW1(const float* __restrict__ W) {
    __shared__ float t[32][33];
    const int tid = threadIdx.x, tx = tid & 31, ty = tid >> 5;
    const int n0 = blockIdx.x * 32, k0 = blockIdx.y * 32;
    #pragma unroll
    for (int i = 0; i < 4; i++)
        t[ty + i * 8][tx] = W[(size_t)(k0 + ty + i * 8) * 512 + n0 + tx];
    __syncthreads();
    #pragma unroll
    for (int i = 0; i < 4; i++) {
        int nl = ty + i * 8;
        float v = t[tx][nl];
        __nv_bfloat16 hi = __float2bfloat16(v);
        g_w1h[(size_t)(n0 + nl) * RAWD + k0 + tx] = hi;
        g_w1l[(size_t)(n0 + nl) * RAWD + k0 + tx] = __float2bfloat16(v - __bfloat162float(hi));
    }
}

__global__ __launch_bounds__(256) void k_features(
    const int* __restrict__ x,
    const float* __restrict__ w_suit, const float* __restrict__ b_suit,
    const float* __restrict__ g_suit, const float* __restrict__ be_suit,
    const float* __restrict__ w_rank, const float* __restrict__ b_rank,
    const float* __restrict__ g_rank, const float* __restrict__ be_rank,
    const float* __restrict__ w_h1, const float* __restrict__ b_h1,
    const float* __restrict__ w_h2, const float* __restrict__ b_h2)
{
    __shared__ float s_wr[400], s_ws[80], s_w1[512], s_w2[1024];
    __shared__ float s_b1[32], s_b2[32];
    __shared__ float s_br[16], s_gr[16], s_ber[16], s_bs[16], s_gs[16], s_bes[16];
    __shared__ int s_rank[9], s_suit[9];
    __shared__ float p_sr[960], p_qr[960], p_ss[960], p_qs[960];
    __shared__ float mu_r[16], si_r[16], mu_s[16], si_s[16];

    const int m = blockIdx.x, tid = threadIdx.x;
    for (int i = tid; i < 400; i += 256) s_wr[i] = w_rank[i];
    for (int i = tid; i < 80;  i += 256) s_ws[i] = w_suit[i];
    for (int i = tid; i < 512; i += 256) s_w1[i] = w_h1[i];
    for (int i = tid; i < 1024; i += 256) s_w2[i] = w_h2[i];
    if (tid < 32) { s_b1[tid] = b_h1[tid]; s_b2[tid] = b_h2[tid]; }
    if (tid < 16) {
        s_br[tid] = b_rank[tid]; s_gr[tid] = g_rank[tid]; s_ber[tid] = be_rank[tid];
        s_bs[tid] = b_suit[tid]; s_gs[tid] = g_suit[tid]; s_bes[tid] = be_suit[tid];
    }
    if (tid == 0) {
        int key[9];
        for (int j = 0; j < 9; j++) {
            int r = x[m * 18 + 2 * j], s = x[m * 18 + 2 * j + 1];
            key[j] = (r << 8) | (s << 4) | j;
        }
        for (int seg = 0; seg < 2; seg++) {
            int lo = seg ? 4 : 0, hi = seg ? 9 : 4;
            for (int a = lo + 1; a < hi; a++) {
                int v = key[a]; int b = a - 1;
                while (b >= lo && key[b] > v) { key[b + 1] = key[b]; b--; }
                key[b + 1] = v;
            }
        }
        for (int j = 0; j < 9; j++) { s_rank[j] = key[j] >> 8; s_suit[j] = (key[j] >> 4) & 15; }
    }
    __syncthreads();

    for (int t = tid; t < 960; t += 256) {
        int n = t >> 4, o = t & 15;
        const int* hp = HP[n / 10];
        const int* bt = BT[n % 10];
        int rk[5] = {s_rank[hp[0]], s_rank[hp[1]], s_rank[bt[0]], s_rank[bt[1]], s_rank[bt[2]]};
        int su[5] = {s_suit[hp[0]], s_suit[hp[1]], s_suit[bt[0]], s_suit[bt[1]], s_suit[bt[2]]};
        float br = s_br[o];
        float lsum = 6.f * br, lsq = 6.f * br * br;
        #pragma unroll
        for (int tt = 0; tt < 5; tt++) {
            float v = br;
            #pragma unroll
            for (int c = 0; c < 5; c++) { int d = rk[c] - tt; if (d >= 0) v += s_wr[o * 25 + c * 5 + d]; }
            lsum += v; lsq += v * v;
        }
        p_sr[t] = lsum; p_qr[t] = lsq;
        float bs = s_bs[o];
        float l2 = 0.f, q2 = 0.f;
        #pragma unroll
        for (int l = 0; l < 5; l++) {
            float v = bs;
            #pragma unroll
            for (int c = 0; c < 5; c++) if (su[c] == l) v += s_ws[o * 5 + c];
            l2 += v; q2 += v * v;
        }
        p_ss[t] = l2; p_qs[t] = q2;
    }
    __syncthreads();
    if (tid < 16) {
        float s = 0.f, q = 0.f;
        for (int n = 0; n < 60; n++) { s += p_sr[n * 16 + tid]; q += p_qr[n * 16 + tid]; }
        float mu = s / 660.f, var = q / 660.f - mu * mu;
        mu_r[tid] = mu; si_r[tid] = rsqrtf(var + 1e-5f) * s_gr[tid];
        s = 0.f; q = 0.f;
        for (int n = 0; n < 60; n++) { s += p_ss[n * 16 + tid]; q += p_qs[n * 16 + tid]; }
        mu = s / 300.f; var = q / 300.f - mu * mu;
        mu_s[tid] = mu; si_s[tid] = rsqrtf(var + 1e-5f) * s_gs[tid];
    }
    __syncthreads();

    for (int t = tid; t < 960; t += 256) {
        int n = t >> 4, o = t & 15;
        const int* hp = HP[n / 10];
        const int* bt = BT[n % 10];
        int rk[5] = {s_rank[hp[0]], s_rank[hp[1]], s_rank[bt[0]], s_rank[bt[1]], s_rank[bt[2]]};
        int su[5] = {s_suit[hp[0]], s_suit[hp[1]], s_suit[bt[0]], s_suit[bt[1]], s_suit[bt[2]]};
        float out16[16];
        float br = s_br[o], mr = mu_r[o], sr = si_r[o], er = s_ber[o];
        #pragma unroll
        for (int tt = 0; tt < 5; tt++) {
            float v = br;
            #pragma unroll
            for (int c = 0; c < 5; c++) { int d = rk[c] - tt; if (d >= 0) v += s_wr[o * 25 + c * 5 + d]; }
            out16[tt] = fmaxf((v - mr) * sr + er, 0.f);
        }
        float z = fmaxf((br - mr) * sr + er, 0.f);
        #pragma unroll
        for (int tt = 5; tt < 11; tt++) out16[tt] = z;
        float bs = s_bs[o], ms = mu_s[o], ss = si_s[o], es = s_bes[o];
        #pragma unroll
        for (int l = 0; l < 5; l++) {
            float v = bs;
            #pragma unroll
            for (int c = 0; c < 5; c++) if (su[c] == l) v += s_ws[o * 5 + c];
            out16[11 + l] = fmaxf((v - ms) * ss + es, 0.f);
        }
        size_t rbase = (size_t)m * RAWD + n * 256 + o * 16;
        #pragma unroll
        for (int i = 0; i < 16; i++) {
            float a = out16[i];
            __nv_bfloat16 hi = __float2bfloat16(a);
            g_rawh[rbase + i] = hi;
            g_rawl[rbase + i] = __float2bfloat16(a - __bfloat162float(hi));
        }
        float h1[32];
        #pragma unroll
        for (int p = 0; p < 32; p++) {
            float a = s_b1[p];
            #pragma unroll
            for (int i = 0; i < 16; i++) a += out16[i] * s_w1[i * 32 + p];
            h1[p] = fmaxf(a, 0.f);
        }
        size_t hbase = ((size_t)(m * 60 + n)) * DH + o * 32;
        float hs = 0.f;
        #pragma unroll
        for (int q = 0; q < 32; q++) {
            float a = s_b2[q];
            #pragma unroll
            for (int p = 0; p < 32; p++) a += h1[p] * s_w2[p * 32 + q];
            a = fmaxf(a, 0.f);
            g_h[hbase + q] = a;
            g_hf[hbase + q] = __float2half_rn(a);
            hs += a;
        }
        hs += __shfl_xor_sync(0xffffffffu, hs, 1);
        hs += __shfl_xor_sync(0xffffffffu, hs, 2);
        hs += __shfl_xor_sync(0xffffffffu, hs, 4);
        hs += __shfl_xor_sync(0xffffffffu, hs, 8);
        if (o == 0) g_hsum[m * 60 + n] = hs;
    }
}

// ---- single-term fp16 tensor GEMM, 128x128 CTA tile, cp.async 4-stage, ldmatrix ----
__global__ __launch_bounds__(256, 2) void k_logits_bf(const float* __restrict__ bcat)
{
    extern __shared__ uint32_t su[];
    const int tid = threadIdx.x, lane = tid & 31, wid = tid >> 5;
    const int wm = wid & 3, wn = wid >> 2;
    const int g = lane >> 2, tg = lane & 3;
    const int row0 = blockIdx.x * 128, col0 = blockIdx.y * 128;
    const uint32_t sbase = (uint32_t)__cvta_generic_to_shared(su);

    float acc[2][8][4];
    #pragma unroll
    for (int mi = 0; mi < 2; mi++)
        #pragma unroll
        for (int nf = 0; nf < 8; nf++)
            #pragma unroll
            for (int c = 0; c < 4; c++) acc[mi][nf][c] = 0.f;

    auto issue = [&](int stg, int s) {
        const int k0 = s * 32;
        const uint32_t sb = sbase + stg * 20480;
        #pragma unroll
        for (int i = 0; i < 2; i++) {
            int c = tid + i * 256;
            int mr = c >> 2, q = c & 3;
            cpa16(sb + (uint32_t)(mr * 80 + q * 16),
                  g_hf + (size_t)(row0 + mr) * 512 + k0 + q * 8);
        }
        #pragma unroll
        for (int i = 0; i < 2; i++) {
            int c = tid + i * 256;
            int nr = c >> 2, q = c & 3;
            cpa16(sb + 10240u + (uint32_t)(nr * 80 + q * 16),
                  g_wf + (size_t)(col0 + nr) * 512 + k0 + q * 8);
        }
        CP_COMMIT();
    };

    const int a_rl = lane & 15;
    const int a_k4 = (lane >> 4) * 4;
    const int b_rl = lane & 7;
    const int b_k4 = ((lane >> 3) & 1) * 4;

    auto compute = [&](int stg) {
        const uint32_t sb = sbase + stg * 20480;
        #pragma unroll
        for (int kq = 0; kq < 16; kq += 8) {
            uint32_t ah[2][4], bf[8][2];
            #pragma unroll
            for (int mi = 0; mi < 2; mi++) {
                int row = wm * 32 + mi * 16 + a_rl;
                ldsm4(ah[mi], sb + (uint32_t)((row * 20 + kq + a_k4) * 4));
            }
            #pragma unroll
            for (int nf = 0; nf < 8; nf++) {
                int row = wn * 64 + nf * 8 + b_rl;
                ldsm2(bf[nf], sb + 10240u + (uint32_t)((row * 20 + kq + b_k4) * 4));
            }
            #pragma unroll
            for (int mi = 0; mi < 2; mi++)
                #pragma unroll
                for (int nf = 0; nf < 8; nf++)
                    mma16h(acc[mi][nf], ah[mi], bf[nf]);
        }
    };

    issue(0, 0);
    issue(1, 1);
    issue(2, 2);
    #pragma unroll 1
    for (int s = 0; s < 16; s++) {
        if (s < 14) { CP_WAIT2(); } else if (s == 14) { CP_WAIT1(); } else { CP_WAIT0(); }
        __syncthreads();
        compute(s & 3);
        if (s + 3 < 16) issue((s + 3) & 3, s + 3);
    }
    __syncthreads();

    float* e_v1 = (float*)su;
    float* e_v2 = (float*)(su + 512);
    int*   e_i1 = (int*)(su + 1024);

    float tv1[4], tv2[4]; int ti1[4];
    #pragma unroll
    for (int q = 0; q < 4; q++) { tv1[q] = -3.0e38f; tv2[q] = -3.0e38f; ti1[q] = 0; }
    #pragma unroll
    for (int nf = 0; nf < 8; nf++) {
        #pragma unroll
        for (int j = 0; j < 2; j++) {
            int gc = col0 + wn * 64 + nf * 8 + tg * 2 + j;
            float bj = (gc < NCAT) ? __ldg(&bcat[gc]) : 0.f;
            #pragma unroll
            for (int mi = 0; mi < 2; mi++)
                #pragma unroll
                for (int hf = 0; hf < 2; hf++) {
                    int q = mi * 2 + hf;
                    float v = (gc < NCAT) ? acc[mi][nf][hf * 2 + j] + bj : -3.0e38f;
                    if (v > tv1[q]) { tv2[q] = tv1[q]; tv1[q] = v; ti1[q] = gc; }
                    else if (v > tv2[q]) tv2[q] = v;
                }
        }
    }
    #pragma unroll
    for (int q = 0; q < 4; q++) {
        float v1 = tv1[q], v2 = tv2[q]; int i1 = ti1[q];
        #pragma unroll
        for (int d = 1; d <= 2; d <<= 1) {
            float ov1 = __shfl_xor_sync(0xffffffffu, v1, d);
            int   oi1 = __shfl_xor_sync(0xffffffffu, i1, d);
            float ov2 = __shfl_xor_sync(0xffffffffu, v2, d);
            if (ov1 > v1)      { v2 = fmaxf(v1, ov2); v1 = ov1; i1 = oi1; }
            else if (ov1 < v1) { v2 = fmaxf(v2, ov1); }
            else               { i1 = min(i1, oi1); v2 = v1; }
        }
        if (tg == 0) {
            int mi = q >> 1, hf = q & 1;
            int lr = wm * 32 + mi * 16 + hf * 8 + g;
            e_v1[lr * 4 + wn] = v1; e_v2[lr * 4 + wn] = v2; e_i1[lr * 4 + wn] = i1;
        }
    }
    __syncthreads();
    if (tid < 128) {
        float v1 = e_v1[tid * 4], v2 = e_v2[tid * 4]; int i1 = e_i1[tid * 4];
        {
            float ov1 = e_v1[tid * 4 + 1], ov2 = e_v2[tid * 4 + 1]; int oi1 = e_i1[tid * 4 + 1];
            if (ov1 > v1)      { v2 = fmaxf(v1, ov2); v1 = ov1; i1 = oi1; }
            else if (ov1 < v1) { v2 = fmaxf(v2, ov1); }
            else               { i1 = min(i1, oi1); v2 = v1; }
        }
        size_t o = (size_t)(row0 + tid) * 64 + blockIdx.y;
        g_t1v[o] = v1; g_t2v[o] = v2; g_t1i[o] = i1;
    }
}

__global__ __launch_bounds__(128) void k_argmax(const float* __restrict__ bcat)
{
    const int row = blockIdx.x, tid = threadIdx.x;
    __shared__ float sh[512];
    __shared__ float s_tv[64], s_t2[64];
    __shared__ int   s_ti[64];
    __shared__ int   s_single[64], s_tiles[64];
    __shared__ int   s_ns, s_nt;
    __shared__ float rbv[128];
    __shared__ int   rbi[128];

    const float* hrow = &g_h[(size_t)row * DH];
    for (int i = tid; i < 512; i += 128) sh[i] = hrow[i];
    if (tid < 64) {
        bool valid = tid < NKT3;
        size_t o = (size_t)row * 64 + tid;
        s_tv[tid] = valid ? g_t1v[o] : -3.0e38f;
        s_t2[tid] = valid ? g_t2v[o] : -3.0e38f;
        s_ti[tid] = valid ? g_t1i[o] : 0;
    }
    __syncthreads();
    if (tid == 0) {
        float gmax = -3.0e38f;
        for (int t = 0; t < NKT3; t++) gmax = fmaxf(gmax, s_tv[t]);
        float wmax = __int_as_float(g_wmax_i);
        float thr = gmax - wmax * g_hsum[row] * 0.001953125f;   // 2^-9 margin
        int ns = 0, nt = 0;
        for (int t = 0; t < NKT3; t++) {
            if (s_tv[t] >= thr) {
                if (s_t2[t] >= thr) s_tiles[nt++] = t;
                else                s_single[ns++] = s_ti[t];
            }
        }
        s_ns = ns; s_nt = nt;
    }
    __syncthreads();

    const int total = s_ns + s_nt * 128;
    float bv = -3.0e38f; int bi = 0x7fffffff;
    for (int e = tid; e < total; e += 128) {
        int col;
        if (e < s_ns) col = s_single[e];
        else { int r = e - s_ns; col = s_tiles[r >> 7] * 128 + (r & 127); }
        if (col < NCAT) {
            float a = bcat[col];
            const float4* wc4 = (const float4*)(g_wt + (size_t)col * 512);
            #pragma unroll 4
            for (int k = 0; k < 128; k++) {
                float4 w = wc4[k];
                a = fmaf(sh[k * 4 + 0], w.x, a);
                a = fmaf(sh[k * 4 + 1], w.y, a);
                a = fmaf(sh[k * 4 + 2], w.z, a);
                a = fmaf(sh[k * 4 + 3], w.w, a);
            }
            if (a > bv || (a == bv && col < bi)) { bv = a; bi = col; }
        }
    }
    rbv[tid] = bv; rbi[tid] = bi;
    __syncthreads();
    if (tid == 0) {
        for (int t = 1; t < 128; t++)
            if (rbv[t] > bv || (rbv[t] == bv && rbi[t] < bi)) { bv = rbv[t]; bi = rbi[t]; }
        atomicMin(&g_bh[row / 60], bi);
    }
}

// ---- rr1: 3-term split-bf16 tensor GEMM (R9-proven) ----
__global__ __launch_bounds__(256, 2) void k_rr1t()
{
    extern __shared__ uint32_t su[];
    const int tid = threadIdx.x, lane = tid & 31, wid = tid >> 5;
    const int wm = wid & 3, wn = wid >> 2;
    const int g = lane >> 2, tg = lane & 3;
    const int row0 = blockIdx.y * 128, col0 = blockIdx.x * 128;
    const int kb = blockIdx.z * (RAWD / RRSPLIT);
    const int NSTEPS = (RAWD / RRSPLIT) / 16;
    const uint32_t sbase = (uint32_t)__cvta_generic_to_shared(su);

    float acc[2][8][4];
    #pragma unroll
    for (int mi = 0; mi < 2; mi++)
        #pragma unroll
        for (int nf = 0; nf < 8; nf++)
            #pragma unroll
            for (int c = 0; c < 4; c++) acc[mi][nf][c] = 0.f;

    const int r = tid >> 1, q = tid & 1;
    auto issue = [&](int stg, int s) {
        const int k0 = kb + s * 16;
        const uint32_t sb = sbase + stg * 24576 + (uint32_t)(r * 48 + q * 16);
        size_t ao = (size_t)(row0 + r) * RAWD + k0 + q * 8;
        size_t bo = (size_t)(col0 + r) * RAWD + k0 + q * 8;
        cpa16(sb,          g_rawh + ao);
        cpa16(sb + 6144u,  g_rawl + ao);
        cpa16(sb + 12288u, g_w1h + bo);
        cpa16(sb + 18432u, g_w1l + bo);
        CP_COMMIT();
    };

    auto compute = [&](int stg) {
        const uint32_t* Ah = su + stg * 6144;
        const uint32_t* Al = Ah + 1536;
        const uint32_t* Bh = Ah + 3072;
        const uint32_t* Bl = Ah + 4608;
        uint32_t ah[2][4], al[2][4], bh[8][2], bl[8][2];
        #pragma unroll
        for (int mi = 0; mi < 2; mi++) {
            int m0 = (wm * 32 + mi * 16 + g) * 12 + tg;
            ah[mi][0] = Ah[m0];     ah[mi][1] = Ah[m0 + 96];
            ah[mi][2] = Ah[m0 + 4]; ah[mi][3] = Ah[m0 + 100];
            al[mi][0] = Al[m0];     al[mi][1] = Al[m0 + 96];
            al[mi][2] = Al[m0 + 4]; al[mi][3] = Al[m0 + 100];
        }
        #pragma unroll
        for (int nf = 0; nf < 8; nf++) {
            int n0 = (wn * 64 + nf * 8 + g) * 12 + tg;
            bh[nf][0] = Bh[n0]; bh[nf][1] = Bh[n0 + 4];
            bl[nf][0] = Bl[n0]; bl[nf][1] = Bl[n0 + 4];
        }
        #pragma unroll
        for (int mi = 0; mi < 2; mi++)
            #pragma unroll
            for (int nf = 0; nf < 8; nf++) {
                mma16(acc[mi][nf], ah[mi], bh[nf]);
                mma16(acc[mi][nf], al[mi], bh[nf]);
                mma16(acc[mi][nf], ah[mi], bl[nf]);
            }
    };

    issue(0, 0);
    issue(1, 1);
    #pragma unroll 1
    for (int s = 0; s < NSTEPS; s++) {
        if (s < NSTEPS - 2) { CP_WAIT1(); } else { CP_WAIT0(); }
        __syncthreads();
        compute(s % 3);
        if (s + 2 < NSTEPS) issue((s + 2) % 3, s + 2);
        __syncthreads();
    }

    #pragma unroll
    for (int mi = 0; mi < 2; mi++)
        #pragma unroll
        for (int nf = 0; nf < 8; nf++)
            #pragma unroll
            for (int c = 0; c < 4; c++) {
                int grow = row0 + wm * 32 + mi * 16 + (c >> 1) * 8 + g;
                int gcol = col0 + wn * 64 + nf * 8 + tg * 2 + (c & 1);
                g_part[((size_t)blockIdx.z * MM + grow) * 512 + gcol] = acc[mi][nf][c];
            }
}

__global__ __launch_bounds__(256) void k_rr1red(const float* __restrict__ b)
{
    int m = blockIdx.x;
    for (int c = threadIdx.x; c < 512; c += 256) {
        float s = 0.f;
        #pragma unroll
        for (int z = 0; z < RRSPLIT; z++)
            s += g_part[((size_t)z * MM + m) * 512 + c];
        g_rr1[m * 512 + c] = fmaxf(s + b[c], 0.f);
    }
}

__global__ __launch_bounds__(256) void k_rr2(const float* __restrict__ W, const float* __restrict__ b)
{
    __shared__ float arow[512];
    int m = blockIdx.x, tid = threadIdx.x;
    for (int i = tid; i < 512; i += 256) arow[i] = g_rr1[m * 512 + i];
    __syncthreads();
    float a = b[tid];
    for (int k = 0; k < 512; k++) a += arow[k] * W[k * 256 + tid];
    g_rr2[m * 256 + tid] = fmaxf(a, 0.f);
}

__global__ __launch_bounds__(128) void k_rr3(const float* __restrict__ W, const float* __restrict__ b)
{
    __shared__ float arow[256];
    int m = blockIdx.x, tid = threadIdx.x;
    for (int i = tid; i < 256; i += 128) arow[i] = g_rr2[m * 256 + i];
    __syncthreads();
    if (tid < 127) {
        float a = b[tid];
        for (int k = 0; k < 256; k++) a += arow[k] * W[k * 127 + tid];
        g_rr3[m * 127 + tid] = fmaxf(a, 0.f);
    }
}

__global__ __launch_bounds__(32) void k_final(const float* __restrict__ w_sc,
                                              const float* __restrict__ b_sc,
                                              float* __restrict__ out)
{
    __shared__ float row[127];
    int m = blockIdx.x, tid = threadIdx.x;
    for (int i = tid; i < 127; i += 32) row[i] = g_rr3[m * 127 + i];
    __syncwarp();
    if (tid < 6) {
        float s = b_sc[tid];
        for (int k = 0; k < 127; k++) s += row[k] * w_sc[k * 6 + tid];
        s += (float)g_bh[m] * w_sc[127 * 6 + tid];
        out[m * 6 + tid] = s;
    }
}

extern "C" void kernel_launch(void* const* d_in, const int* in_sizes, int n_in,
                              void* d_out, int out_size)
{
    const int*   x      = (const int*)d_in[0];
    const float* w_suit = (const float*)d_in[1];
    const float* b_suit = (const float*)d_in[2];
    const float* gg_s   = (const float*)d_in[3];
    const float* be_s   = (const float*)d_in[4];
    const float* w_rank = (const float*)d_in[5];
    const float* b_rank = (const float*)d_in[6];
    const float* gg_r   = (const float*)d_in[7];
    const float* be_r   = (const float*)d_in[8];
    const float* w_h1   = (const float*)d_in[9];
    const float* b_h1   = (const float*)d_in[10];
    const float* w_h2   = (const float*)d_in[11];
    const float* b_h2   = (const float*)d_in[12];
    const float* w_cat  = (const float*)d_in[13];
    const float* b_cat  = (const float*)d_in[14];
    const float* w_o1   = (const float*)d_in[15];
    const float* b_o1   = (const float*)d_in[16];
    const float* w_o2   = (const float*)d_in[17];
    const float* b_o2   = (const float*)d_in[18];
    const float* w_o3   = (const float*)d_in[19];
    const float* b_o3   = (const float*)d_in[20];
    const float* w_sc   = (const float*)d_in[21];
    const float* b_sc   = (const float*)d_in[22];
    float* out = (float*)d_out;

    static cudaStream_t s1 = nullptr;
    static cudaEvent_t evS = nullptr, evF = nullptr, evJ = nullptr, evP = nullptr;
    if (!s1) {
        cudaStreamCreateWithFlags(&s1, cudaStreamNonBlocking);
        cudaEventCreateWithFlags(&evS, cudaEventDisableTiming);
        cudaEventCreateWithFlags(&evF, cudaEventDisableTiming);
        cudaEventCreateWithFlags(&evJ, cudaEventDisableTiming);
        cudaEventCreateWithFlags(&evP, cudaEventDisableTiming);
        cudaFuncSetAttribute(k_logits_bf, cudaFuncAttributeMaxDynamicSharedMemorySize, LOG_SMEM);
        cudaFuncSetAttribute(k_rr1t, cudaFuncAttributeMaxDynamicSharedMemorySize, RR1_SMEM);
    }

    k_init<<<2, 256>>>();
    cudaEventRecord(evS, 0);
    cudaStreamWaitEvent(s1, evS, 0);

    dim3 gpw(NPADB / 32, 16);
    k_packWb<<<gpw, 256, 0, s1>>>(w_cat);
    cudaEventRecord(evP, s1);
    dim3 gp1(16, RAWD / 32);
    k_packW1<<<gp1, 256, 0, s1>>>(w_o1);

    k_features<<<MM, 256>>>(x, w_suit, b_suit, gg_s, be_s,
                            w_rank, b_rank, gg_r, be_r,
                            w_h1, b_h1, w_h2, b_h2);
    cudaEventRecord(evF, 0);
    cudaStreamWaitEvent(s1, evF, 0);

    dim3 g41(4, 4, RRSPLIT);
    k_rr1t<<<g41, 256, RR1_SMEM, s1>>>();
    k_rr1red<<<MM, 256, 0, s1>>>(b_o1);
    k_rr2<<<MM, 256, 0, s1>>>(w_o2, b_o2);
    k_rr3<<<MM, 128, 0, s1>>>(w_o3, b_o3);
    cudaEventRecord(evJ, s1);

    cudaStreamWaitEvent(0, evP, 0);
    dim3 gl(NROWS / 128, NKT3);
    k_logits_bf<<<gl, 256, LOG_SMEM>>>(b_cat);
    k_argmax<<<NROWS, 128>>>(b_cat);

    cudaStreamWaitEvent(0, evJ, 0);
    k_final<<<MM, 32>>>(w_sc, b_sc, out);
}

// round 15
// speedup vs baseline: 1.1208x; 1.0315x over previous
#include <cuda_runtime.h>
#include <cuda_bf16.h>
#include <cuda_fp16.h>
#include <cstdint>

#define MM 512
#define NCOMBO 60
#define NCAT 7463
#define DH 512
#define RAWD 15360
#define NROWS (MM * NCOMBO)
#define NKT3 59
#define NPADB (NKT3 * 128)
#define LOG_SMEM 81920          /* 4 stages x 20480B */
#define RR1_SMEM 73728
#define RRSPLIT 8

__device__ __align__(16) float g_h[(size_t)NROWS * DH];
__device__ __align__(16) __half g_hf[(size_t)NROWS * DH];
__device__ __align__(16) __half g_wf[(size_t)NPADB * DH];
__device__ __align__(16) float g_wt[(size_t)NPADB * DH];
__device__ __align__(16) __nv_bfloat16 g_rawh[(size_t)MM * RAWD];
__device__ __align__(16) __nv_bfloat16 g_rawl[(size_t)MM * RAWD];
__device__ __align__(16) __nv_bfloat16 g_w1h[(size_t)MM * RAWD];
__device__ __align__(16) __nv_bfloat16 g_w1l[(size_t)MM * RAWD];
__device__ __align__(16) float g_part[RRSPLIT * MM * 512];
__device__ __align__(16) float g_rr1[MM * 512];
__device__ __align__(16) float g_rr2[MM * 256];
__device__ __align__(16) float g_rr3[MM * 127];
__device__ int   g_bh[MM];
__device__ float g_hsum[NROWS];
__device__ __align__(16) float g_t1v[(size_t)NROWS * 64];
__device__ __align__(16) float g_t2v[(size_t)NROWS * 64];
__device__ __align__(16) int   g_t1i[(size_t)NROWS * 64];
__device__ int g_wmax_i;

__constant__ int HP[6][2] = {{0,1},{0,2},{0,3},{1,2},{1,3},{2,3}};
__constant__ int BT[10][3] = {{4,5,6},{4,5,7},{4,5,8},{4,6,7},{4,6,8},
                              {4,7,8},{5,6,7},{5,6,8},{5,7,8},{6,7,8}};

__device__ __forceinline__ void mma16(float* d, const uint32_t* a, const uint32_t* b) {
    asm volatile("mma.sync.aligned.m16n8k16.row.col.f32.bf16.bf16.f32 "
                 "{%0,%1,%2,%3}, {%4,%5,%6,%7}, {%8,%9}, {%0,%1,%2,%3};"
                 : "+f"(d[0]), "+f"(d[1]), "+f"(d[2]), "+f"(d[3])
                 : "r"(a[0]), "r"(a[1]), "r"(a[2]), "r"(a[3]), "r"(b[0]), "r"(b[1]));
}
__device__ __forceinline__ void mma16h(float* d, const uint32_t* a, const uint32_t* b) {
    asm volatile("mma.sync.aligned.m16n8k16.row.col.f32.f16.f16.f32 "
                 "{%0,%1,%2,%3}, {%4,%5,%6,%7}, {%8,%9}, {%0,%1,%2,%3};"
                 : "+f"(d[0]), "+f"(d[1]), "+f"(d[2]), "+f"(d[3])
                 : "r"(a[0]), "r"(a[1]), "r"(a[2]), "r"(a[3]), "r"(b[0]), "r"(b[1]));
}
__device__ __forceinline__ void ldsm4(uint32_t* r, uint32_t addr) {
    asm volatile("ldmatrix.sync.aligned.m8n8.x4.shared.b16 {%0,%1,%2,%3}, [%4];"
                 : "=r"(r[0]), "=r"(r[1]), "=r"(r[2]), "=r"(r[3]) : "r"(addr));
}
__device__ __forceinline__ void cpa16(uint32_t dst, const void* src) {
    asm volatile("cp.async.ca.shared.global [%0], [%1], 16;" :: "r"(dst), "l"(src));
}
#define CP_COMMIT() asm volatile("cp.async.commit_group;" ::: "memory")
#define CP_WAIT2()  asm volatile("cp.async.wait_group 2;" ::: "memory")
#define CP_WAIT1()  asm volatile("cp.async.wait_group 1;" ::: "memory")
#define CP_WAIT0()  asm volatile("cp.async.wait_group 0;" ::: "memory")

__global__ void k_init() {
    int i = blockIdx.x * blockDim.x + threadIdx.x;
    if (i == 0) g_wmax_i = 0;
    if (i < MM) g_bh[i] = 0x7fffffff;
}

__global__ __launch_bounds__(256) void k_packWb(const float* __restrict__ W) {
    __shared__ float t[32][33];
    const int tid = threadIdx.x, tx = tid & 31, ty = tid >> 5;
    const int n0 = blockIdx.x * 32, k0 = blockIdx.y * 32;
    float lm = 0.f;
    #pragma unroll
    for (int i = 0; i < 4; i++) {
        int k = k0 + ty + i * 8, n = n0 + tx;
        float w = (n < NCAT) ? W[(size_t)k * NCAT + n] : 0.f;
        t[ty + i * 8][tx] = w;
        lm = fmaxf(lm, fabsf(w));
    }
    __syncthreads();
    #pragma unroll
    for (int i = 0; i < 4; i++) {
        int nl = ty + i * 8;
        float v = t[tx][nl];
        g_wf[(size_t)(n0 + nl) * 512 + k0 + tx] = __float2half_rn(v);
        g_wt[(size_t)(n0 + nl) * 512 + k0 + tx] = v;
    }
    #pragma unroll
    for (int d = 16; d; d >>= 1) lm = fmaxf(lm, __shfl_xor_sync(0xffffffffu, lm, d));
    if ((tid & 31) == 0) atomicMax(&g_wmax_i, __float_as_int(lm));
}

__global__ __launch_bounds__(256) void k_packW1(const float* __restrict__ W) {
    __shared__ float t[32][33];
    const int tid = threadIdx.x, tx = tid & 31, ty = tid >> 5;
    const int n0 = blockIdx.x * 32, k0 = blockIdx.y * 32;
    #pragma unroll
    for (int i = 0; i < 4; i++)
        t[ty + i * 8][tx] = W[(size_t)(k0 + ty + i * 8) * 512 + n0 + tx];
    __syncthreads();
    #pragma unroll
    for (int i = 0; i < 4; i++) {
        int nl = ty + i * 8;
        float v = t[tx][nl];
        __nv_bfloat16 hi = __float2bfloat16(v);
        g_w1h[(size_t)(n0 + nl) * RAWD + k0 + tx] = hi;
        g_w1l[(size_t)(n0 + nl) * RAWD + k0 + tx] = __float2bfloat16(v - __bfloat162float(hi));
    }
}

__global__ __launch_bounds__(256) void k_features(
    const int* __restrict__ x,
    const float* __restrict__ w_suit, const float* __restrict__ b_suit,
    const float* __restrict__ g_suit, const float* __restrict__ be_suit,
    const float* __restrict__ w_rank, const float* __restrict__ b_rank,
    const float* __restrict__ g_rank, const float* __restrict__ be_rank,
    const float* __restrict__ w_h1, const float* __restrict__ b_h1,
    const float* __restrict__ w_h2, const float* __restrict__ b_h2)
{
    __shared__ float s_wr[400], s_ws[80], s_w1[512], s_w2[1024];
    __shared__ float s_b1[32], s_b2[32];
    __shared__ float s_br[16], s_gr[16], s_ber[16], s_bs[16], s_gs[16], s_bes[16];
    __shared__ int s_rank[9], s_suit[9];
    __shared__ float p_sr[960], p_qr[960], p_ss[960], p_qs[960];
    __shared__ float mu_r[16], si_r[16], mu_s[16], si_s[16];

    const int m = blockIdx.x, tid = threadIdx.x;
    for (int i = tid; i < 400; i += 256) s_wr[i] = w_rank[i];
    for (int i = tid; i < 80;  i += 256) s_ws[i] = w_suit[i];
    for (int i = tid; i < 512; i += 256) s_w1[i] = w_h1[i];
    for (int i = tid; i < 1024; i += 256) s_w2[i] = w_h2[i];
    if (tid < 32) { s_b1[tid] = b_h1[tid]; s_b2[tid] = b_h2[tid]; }
    if (tid < 16) {
        s_br[tid] = b_rank[tid]; s_gr[tid] = g_rank[tid]; s_ber[tid] = be_rank[tid];
        s_bs[tid] = b_suit[tid]; s_gs[tid] = g_suit[tid]; s_bes[tid] = be_suit[tid];
    }
    if (tid == 0) {
        int key[9];
        for (int j = 0; j < 9; j++) {
            int r = x[m * 18 + 2 * j], s = x[m * 18 + 2 * j + 1];
            key[j] = (r << 8) | (s << 4) | j;
        }
        for (int seg = 0; seg < 2; seg++) {
            int lo = seg ? 4 : 0, hi = seg ? 9 : 4;
            for (int a = lo + 1; a < hi; a++) {
                int v = key[a]; int b = a - 1;
                while (b >= lo && key[b] > v) { key[b + 1] = key[b]; b--; }
                key[b + 1] = v;
            }
        }
        for (int j = 0; j < 9; j++) { s_rank[j] = key[j] >> 8; s_suit[j] = (key[j] >> 4) & 15; }
    }
    __syncthreads();

    for (int t = tid; t < 960; t += 256) {
        int n = t >> 4, o = t & 15;
        const int* hp = HP[n / 10];
        const int* bt = BT[n % 10];
        int rk[5] = {s_rank[hp[0]], s_rank[hp[1]], s_rank[bt[0]], s_rank[bt[1]], s_rank[bt[2]]};
        int su[5] = {s_suit[hp[0]], s_suit[hp[1]], s_suit[bt[0]], s_suit[bt[1]], s_suit[bt[2]]};
        float br = s_br[o];
        float lsum = 6.f * br, lsq = 6.f * br * br;
        #pragma unroll
        for (int tt = 0; tt < 5; tt++) {
            float v = br;
            #pragma unroll
            for (int c = 0; c < 5; c++) { int d = rk[c] - tt; if (d >= 0) v += s_wr[o * 25 + c * 5 + d]; }
            lsum += v; lsq += v * v;
        }
        p_sr[t] = lsum; p_qr[t] = lsq;
        float bs = s_bs[o];
        float l2 = 0.f, q2 = 0.f;
        #pragma unroll
        for (int l = 0; l < 5; l++) {
            float v = bs;
            #pragma unroll
            for (int c = 0; c < 5; c++) if (su[c] == l) v += s_ws[o * 5 + c];
            l2 += v; q2 += v * v;
        }
        p_ss[t] = l2; p_qs[t] = q2;
    }
    __syncthreads();
    if (tid < 16) {
        float s = 0.f, q = 0.f;
        for (int n = 0; n < 60; n++) { s += p_sr[n * 16 + tid]; q += p_qr[n * 16 + tid]; }
        float mu = s / 660.f, var = q / 660.f - mu * mu;
        mu_r[tid] = mu; si_r[tid] = rsqrtf(var + 1e-5f) * s_gr[tid];
        s = 0.f; q = 0.f;
        for (int n = 0; n < 60; n++) { s += p_ss[n * 16 + tid]; q += p_qs[n * 16 + tid]; }
        mu = s / 300.f; var = q / 300.f - mu * mu;
        mu_s[tid] = mu; si_s[tid] = rsqrtf(var + 1e-5f) * s_gs[tid];
    }
    __syncthreads();

    for (int t = tid; t < 960; t += 256) {
        int n = t >> 4, o = t & 15;
        const int* hp = HP[n / 10];
        const int* bt = BT[n % 10];
        int rk[5] = {s_rank[hp[0]], s_rank[hp[1]], s_rank[bt[0]], s_rank[bt[1]], s_rank[bt[2]]};
        int su[5] = {s_suit[hp[0]], s_suit[hp[1]], s_suit[bt[0]], s_suit[bt[1]], s_suit[bt[2]]};
        float out16[16];
        float br = s_br[o], mr = mu_r[o], sr = si_r[o], er = s_ber[o];
        #pragma unroll
        for (int tt = 0; tt < 5; tt++) {
            float v = br;
            #pragma unroll
            for (int c = 0; c < 5; c++) { int d = rk[c] - tt; if (d >= 0) v += s_wr[o * 25 + c * 5 + d]; }
            out16[tt] = fmaxf((v - mr) * sr + er, 0.f);
        }
        float z = fmaxf((br - mr) * sr + er, 0.f);
        #pragma unroll
        for (int tt = 5; tt < 11; tt++) out16[tt] = z;
        float bs = s_bs[o], ms = mu_s[o], ss = si_s[o], es = s_bes[o];
        #pragma unroll
        for (int l = 0; l < 5; l++) {
            float v = bs;
            #pragma unroll
            for (int c = 0; c < 5; c++) if (su[c] == l) v += s_ws[o * 5 + c];
            out16[11 + l] = fmaxf((v - ms) * ss + es, 0.f);
        }
        size_t rbase = (size_t)m * RAWD + n * 256 + o * 16;
        #pragma unroll
        for (int i = 0; i < 16; i++) {
            float a = out16[i];
            __nv_bfloat16 hi = __float2bfloat16(a);
            g_rawh[rbase + i] = hi;
            g_rawl[rbase + i] = __float2bfloat16(a - __bfloat162float(hi));
        }
        float h1[32];
        #pragma unroll
        for (int p = 0; p < 32; p++) {
            float a = s_b1[p];
            #pragma unroll
            for (int i = 0; i < 16; i++) a += out16[i] * s_w1[i * 32 + p];
            h1[p] = fmaxf(a, 0.f);
        }
        size_t hbase = ((size_t)(m * 60 + n)) * DH + o * 32;
        float hs = 0.f;
        #pragma unroll
        for (int q = 0; q < 32; q++) {
            float a = s_b2[q];
            #pragma unroll
            for (int p = 0; p < 32; p++) a += h1[p] * s_w2[p * 32 + q];
            a = fmaxf(a, 0.f);
            g_h[hbase + q] = a;
            g_hf[hbase + q] = __float2half_rn(a);
            hs += a;
        }
        hs += __shfl_xor_sync(0xffffffffu, hs, 1);
        hs += __shfl_xor_sync(0xffffffffu, hs, 2);
        hs += __shfl_xor_sync(0xffffffffu, hs, 4);
        hs += __shfl_xor_sync(0xffffffffu, hs, 8);
        if (o == 0) g_hsum[m * 60 + n] = hs;
    }
}

// ---- single-term fp16 tensor GEMM, 128x128 CTA tile, cp.async 4-stage, ldmatrix ----
__global__ __launch_bounds__(256, 2) void k_logits_bf(const float* __restrict__ bcat)
{
    extern __shared__ uint32_t su[];
    const int tid = threadIdx.x, lane = tid & 31, wid = tid >> 5;
    const int wm = wid & 3, wn = wid >> 2;
    const int g = lane >> 2, tg = lane & 3;
    const int row0 = blockIdx.x * 128, col0 = blockIdx.y * 128;
    const uint32_t sbase = (uint32_t)__cvta_generic_to_shared(su);

    float acc[2][8][4];
    #pragma unroll
    for (int mi = 0; mi < 2; mi++)
        #pragma unroll
        for (int nf = 0; nf < 8; nf++)
            #pragma unroll
            for (int c = 0; c < 4; c++) acc[mi][nf][c] = 0.f;

    auto issue = [&](int stg, int s) {
        const int k0 = s * 32;
        const uint32_t sb = sbase + stg * 20480;
        #pragma unroll
        for (int i = 0; i < 2; i++) {
            int c = tid + i * 256;
            int mr = c >> 2, q = c & 3;
            cpa16(sb + (uint32_t)(mr * 80 + q * 16),
                  g_hf + (size_t)(row0 + mr) * 512 + k0 + q * 8);
        }
        #pragma unroll
        for (int i = 0; i < 2; i++) {
            int c = tid + i * 256;
            int nr = c >> 2, q = c & 3;
            cpa16(sb + 10240u + (uint32_t)(nr * 80 + q * 16),
                  g_wf + (size_t)(col0 + nr) * 512 + k0 + q * 8);
        }
        CP_COMMIT();
    };

    const int a_rl = lane & 15;
    const int a_k4 = (lane >> 4) * 4;
    const int b_rl = lane & 7;
    const int b_k4 = ((lane >> 3) & 1) * 4;
    const int b_nh = (lane >> 4) & 1;          // which nf of the pair this lane addresses

    auto compute = [&](int stg) {
        const uint32_t sb = sbase + stg * 20480;
        #pragma unroll
        for (int kq = 0; kq < 16; kq += 8) {
            uint32_t ah[2][4], bf[8][2];
            #pragma unroll
            for (int mi = 0; mi < 2; mi++) {
                int row = wm * 32 + mi * 16 + a_rl;
                ldsm4(ah[mi], sb + (uint32_t)((row * 20 + kq + a_k4) * 4));
            }
            #pragma unroll
            for (int nf = 0; nf < 8; nf += 2) {
                int row = wn * 64 + (nf + b_nh) * 8 + b_rl;
                uint32_t r[4];
                ldsm4(r, sb + 10240u + (uint32_t)((row * 20 + kq + b_k4) * 4));
                bf[nf][0] = r[0]; bf[nf][1] = r[1];
                bf[nf + 1][0] = r[2]; bf[nf + 1][1] = r[3];
            }
            #pragma unroll
            for (int mi = 0; mi < 2; mi++)
                #pragma unroll
                for (int nf = 0; nf < 8; nf++)
                    mma16h(acc[mi][nf], ah[mi], bf[nf]);
        }
    };

    issue(0, 0);
    issue(1, 1);
    issue(2, 2);
    #pragma unroll 1
    for (int s = 0; s < 16; s++) {
        if (s < 14) { CP_WAIT2(); } else if (s == 14) { CP_WAIT1(); } else { CP_WAIT0(); }
        __syncthreads();
        compute(s & 3);
        if (s + 3 < 16) issue((s + 3) & 3, s + 3);
    }
    __syncthreads();

    float* e_v1 = (float*)su;
    float* e_v2 = (float*)(su + 512);
    int*   e_i1 = (int*)(su + 1024);

    float tv1[4], tv2[4]; int ti1[4];
    #pragma unroll
    for (int q = 0; q < 4; q++) { tv1[q] = -3.0e38f; tv2[q] = -3.0e38f; ti1[q] = 0; }
    #pragma unroll
    for (int nf = 0; nf < 8; nf++) {
        #pragma unroll
        for (int j = 0; j < 2; j++) {
            int gc = col0 + wn * 64 + nf * 8 + tg * 2 + j;
            float bj = (gc < NCAT) ? __ldg(&bcat[gc]) : 0.f;
            #pragma unroll
            for (int mi = 0; mi < 2; mi++)
                #pragma unroll
                for (int hf = 0; hf < 2; hf++) {
                    int q = mi * 2 + hf;
                    float v = (gc < NCAT) ? acc[mi][nf][hf * 2 + j] + bj : -3.0e38f;
                    if (v > tv1[q]) { tv2[q] = tv1[q]; tv1[q] = v; ti1[q] = gc; }
                    else if (v > tv2[q]) tv2[q] = v;
                }
        }
    }
    #pragma unroll
    for (int q = 0; q < 4; q++) {
        float v1 = tv1[q], v2 = tv2[q]; int i1 = ti1[q];
        #pragma unroll
        for (int d = 1; d <= 2; d <<= 1) {
            float ov1 = __shfl_xor_sync(0xffffffffu, v1, d);
            int   oi1 = __shfl_xor_sync(0xffffffffu, i1, d);
            float ov2 = __shfl_xor_sync(0xffffffffu, v2, d);
            if (ov1 > v1)      { v2 = fmaxf(v1, ov2); v1 = ov1; i1 = oi1; }
            else if (ov1 < v1) { v2 = fmaxf(v2, ov1); }
            else               { i1 = min(i1, oi1); v2 = v1; }
        }
        if (tg == 0) {
            int mi = q >> 1, hf = q & 1;
            int lr = wm * 32 + mi * 16 + hf * 8 + g;
            e_v1[lr * 4 + wn] = v1; e_v2[lr * 4 + wn] = v2; e_i1[lr * 4 + wn] = i1;
        }
    }
    __syncthreads();
    if (tid < 128) {
        float v1 = e_v1[tid * 4], v2 = e_v2[tid * 4]; int i1 = e_i1[tid * 4];
        {
            float ov1 = e_v1[tid * 4 + 1], ov2 = e_v2[tid * 4 + 1]; int oi1 = e_i1[tid * 4 + 1];
            if (ov1 > v1)      { v2 = fmaxf(v1, ov2); v1 = ov1; i1 = oi1; }
            else if (ov1 < v1) { v2 = fmaxf(v2, ov1); }
            else               { i1 = min(i1, oi1); v2 = v1; }
        }
        size_t o = (size_t)(row0 + tid) * 64 + blockIdx.y;
        g_t1v[o] = v1; g_t2v[o] = v2; g_t1i[o] = i1;
    }
}

__global__ __launch_bounds__(128) void k_argmax(const float* __restrict__ bcat)
{
    const int row = blockIdx.x, tid = threadIdx.x;
    __shared__ float sh[512];
    __shared__ float s_tv[64], s_t2[64];
    __shared__ int   s_ti[64];
    __shared__ int   s_single[64], s_tiles[64];
    __shared__ int   s_ns, s_nt;
    __shared__ float rbv[128];
    __shared__ int   rbi[128];

    const float* hrow = &g_h[(size_t)row * DH];
    for (int i = tid; i < 512; i += 128) sh[i] = hrow[i];
    if (tid < 64) {
        bool valid = tid < NKT3;
        size_t o = (size_t)row * 64 + tid;
        s_tv[tid] = valid ? g_t1v[o] : -3.0e38f;
        s_t2[tid] = valid ? g_t2v[o] : -3.0e38f;
        s_ti[tid] = valid ? g_t1i[o] : 0;
    }
    __syncthreads();
    if (tid == 0) {
        float gmax = -3.0e38f;
        for (int t = 0; t < NKT3; t++) gmax = fmaxf(gmax, s_tv[t]);
        float wmax = __int_as_float(g_wmax_i);
        float thr = gmax - wmax * g_hsum[row] * 0.001953125f;   // 2^-9 margin
        int ns = 0, nt = 0;
        for (int t = 0; t < NKT3; t++) {
            if (s_tv[t] >= thr) {
                if (s_t2[t] >= thr) s_tiles[nt++] = t;
                else                s_single[ns++] = s_ti[t];
            }
        }
        s_ns = ns; s_nt = nt;
    }
    __syncthreads();

    const int total = s_ns + s_nt * 128;
    float bv = -3.0e38f; int bi = 0x7fffffff;
    for (int e = tid; e < total; e += 128) {
        int col;
        if (e < s_ns) col = s_single[e];
        else { int r = e - s_ns; col = s_tiles[r >> 7] * 128 + (r & 127); }
        if (col < NCAT) {
            float a = bcat[col];
            const float4* wc4 = (const float4*)(g_wt + (size_t)col * 512);
            #pragma unroll 4
            for (int k = 0; k < 128; k++) {
                float4 w = wc4[k];
                a = fmaf(sh[k * 4 + 0], w.x, a);
                a = fmaf(sh[k * 4 + 1], w.y, a);
                a = fmaf(sh[k * 4 + 2], w.z, a);
                a = fmaf(sh[k * 4 + 3], w.w, a);
            }
            if (a > bv || (a == bv && col < bi)) { bv = a; bi = col; }
        }
    }
    rbv[tid] = bv; rbi[tid] = bi;
    __syncthreads();
    if (tid == 0) {
        for (int t = 1; t < 128; t++)
            if (rbv[t] > bv || (rbv[t] == bv && rbi[t] < bi)) { bv = rbv[t]; bi = rbi[t]; }
        atomicMin(&g_bh[row / 60], bi);
    }
}

// ---- rr1: 3-term split-bf16 tensor GEMM (R9-proven) ----
__global__ __launch_bounds__(256, 2) void k_rr1t()
{
    extern __shared__ uint32_t su[];
    const int tid = threadIdx.x, lane = tid & 31, wid = tid >> 5;
    const int wm = wid & 3, wn = wid >> 2;
    const int g = lane >> 2, tg = lane & 3;
    const int row0 = blockIdx.y * 128, col0 = blockIdx.x * 128;
    const int kb = blockIdx.z * (RAWD / RRSPLIT);
    const int NSTEPS = (RAWD / RRSPLIT) / 16;
    const uint32_t sbase = (uint32_t)__cvta_generic_to_shared(su);

    float acc[2][8][4];
    #pragma unroll
    for (int mi = 0; mi < 2; mi++)
        #pragma unroll
        for (int nf = 0; nf < 8; nf++)
            #pragma unroll
            for (int c = 0; c < 4; c++) acc[mi][nf][c] = 0.f;

    const int r = tid >> 1, q = tid & 1;
    auto issue = [&](int stg, int s) {
        const int k0 = kb + s * 16;
        const uint32_t sb = sbase + stg * 24576 + (uint32_t)(r * 48 + q * 16);
        size_t ao = (size_t)(row0 + r) * RAWD + k0 + q * 8;
        size_t bo = (size_t)(col0 + r) * RAWD + k0 + q * 8;
        cpa16(sb,          g_rawh + ao);
        cpa16(sb + 6144u,  g_rawl + ao);
        cpa16(sb + 12288u, g_w1h + bo);
        cpa16(sb + 18432u, g_w1l + bo);
        CP_COMMIT();
    };

    auto compute = [&](int stg) {
        const uint32_t* Ah = su + stg * 6144;
        const uint32_t* Al = Ah + 1536;
        const uint32_t* Bh = Ah + 3072;
        const uint32_t* Bl = Ah + 4608;
        uint32_t ah[2][4], al[2][4], bh[8][2], bl[8][2];
        #pragma unroll
        for (int mi = 0; mi < 2; mi++) {
            int m0 = (wm * 32 + mi * 16 + g) * 12 + tg;
            ah[mi][0] = Ah[m0];     ah[mi][1] = Ah[m0 + 96];
            ah[mi][2] = Ah[m0 + 4]; ah[mi][3] = Ah[m0 + 100];
            al[mi][0] = Al[m0];     al[mi][1] = Al[m0 + 96];
            al[mi][2] = Al[m0 + 4]; al[mi][3] = Al[m0 + 100];
        }
        #pragma unroll
        for (int nf = 0; nf < 8; nf++) {
            int n0 = (wn * 64 + nf * 8 + g) * 12 + tg;
            bh[nf][0] = Bh[n0]; bh[nf][1] = Bh[n0 + 4];
            bl[nf][0] = Bl[n0]; bl[nf][1] = Bl[n0 + 4];
        }
        #pragma unroll
        for (int mi = 0; mi < 2; mi++)
            #pragma unroll
            for (int nf = 0; nf < 8; nf++) {
                mma16(acc[mi][nf], ah[mi], bh[nf]);
                mma16(acc[mi][nf], al[mi], bh[nf]);
                mma16(acc[mi][nf], ah[mi], bl[nf]);
            }
    };

    issue(0, 0);
    issue(1, 1);
    #pragma unroll 1
    for (int s = 0; s < NSTEPS; s++) {
        if (s < NSTEPS - 2) { CP_WAIT1(); } else { CP_WAIT0(); }
        __syncthreads();
        compute(s % 3);
        if (s + 2 < NSTEPS) issue((s + 2) % 3, s + 2);
        __syncthreads();
    }

    #pragma unroll
    for (int mi = 0; mi < 2; mi++)
        #pragma unroll
        for (int nf = 0; nf < 8; nf++)
            #pragma unroll
            for (int c = 0; c < 4; c++) {
                int grow = row0 + wm * 32 + mi * 16 + (c >> 1) * 8 + g;
                int gcol = col0 + wn * 64 + nf * 8 + tg * 2 + (c & 1);
                g_part[((size_t)blockIdx.z * MM + grow) * 512 + gcol] = acc[mi][nf][c];
            }
}

__global__ __launch_bounds__(256) void k_rr1red(const float* __restrict__ b)
{
    int m = blockIdx.x;
    for (int c = threadIdx.x; c < 512; c += 256) {
        float s = 0.f;
        #pragma unroll
        for (int z = 0; z < RRSPLIT; z++)
            s += g_part[((size_t)z * MM + m) * 512 + c];
        g_rr1[m * 512 + c] = fmaxf(s + b[c], 0.f);
    }
}

__global__ __launch_bounds__(256) void k_rr2(const float* __restrict__ W, const float* __restrict__ b)
{
    __shared__ float arow[512];
    int m = blockIdx.x, tid = threadIdx.x;
    for (int i = tid; i < 512; i += 256) arow[i] = g_rr1[m * 512 + i];
    __syncthreads();
    float a = b[tid];
    for (int k = 0; k < 512; k++) a += arow[k] * W[k * 256 + tid];
    g_rr2[m * 256 + tid] = fmaxf(a, 0.f);
}

__global__ __launch_bounds__(128) void k_rr3(const float* __restrict__ W, const float* __restrict__ b)
{
    __shared__ float arow[256];
    int m = blockIdx.x, tid = threadIdx.x;
    for (int i = tid; i < 256; i += 128) arow[i] = g_rr2[m * 256 + i];
    __syncthreads();
    if (tid < 127) {
        float a = b[tid];
        for (int k = 0; k < 256; k++) a += arow[k] * W[k * 127 + tid];
        g_rr3[m * 127 + tid] = fmaxf(a, 0.f);
    }
}

__global__ __launch_bounds__(32) void k_final(const float* __restrict__ w_sc,
                                              const float* __restrict__ b_sc,
                                              float* __restrict__ out)
{
    __shared__ float row[127];
    int m = blockIdx.x, tid = threadIdx.x;
    for (int i = tid; i < 127; i += 32) row[i] = g_rr3[m * 127 + i];
    __syncwarp();
    if (tid < 6) {
        float s = b_sc[tid];
        for (int k = 0; k < 127; k++) s += row[k] * w_sc[k * 6 + tid];
        s += (float)g_bh[m] * w_sc[127 * 6 + tid];
        out[m * 6 + tid] = s;
    }
}

extern "C" void kernel_launch(void* const* d_in, const int* in_sizes, int n_in,
                              void* d_out, int out_size)
{
    const int*   x      = (const int*)d_in[0];
    const float* w_suit = (const float*)d_in[1];
    const float* b_suit = (const float*)d_in[2];
    const float* gg_s   = (const float*)d_in[3];
    const float* be_s   = (const float*)d_in[4];
    const float* w_rank = (const float*)d_in[5];
    const float* b_rank = (const float*)d_in[6];
    const float* gg_r   = (const float*)d_in[7];
    const float* be_r   = (const float*)d_in[8];
    const float* w_h1   = (const float*)d_in[9];
    const float* b_h1   = (const float*)d_in[10];
    const float* w_h2   = (const float*)d_in[11];
    const float* b_h2   = (const float*)d_in[12];
    const float* w_cat  = (const float*)d_in[13];
    const float* b_cat  = (const float*)d_in[14];
    const float* w_o1   = (const float*)d_in[15];
    const float* b_o1   = (const float*)d_in[16];
    const float* w_o2   = (const float*)d_in[17];
    const float* b_o2   = (const float*)d_in[18];
    const float* w_o3   = (const float*)d_in[19];
    const float* b_o3   = (const float*)d_in[20];
    const float* w_sc   = (const float*)d_in[21];
    const float* b_sc   = (const float*)d_in[22];
    float* out = (float*)d_out;

    static cudaStream_t s1 = nullptr;
    static cudaEvent_t evS = nullptr, evF = nullptr, evJ = nullptr, evP = nullptr;
    if (!s1) {
        cudaStreamCreateWithFlags(&s1, cudaStreamNonBlocking);
        cudaEventCreateWithFlags(&evS, cudaEventDisableTiming);
        cudaEventCreateWithFlags(&evF, cudaEventDisableTiming);
        cudaEventCreateWithFlags(&evJ, cudaEventDisableTiming);
        cudaEventCreateWithFlags(&evP, cudaEventDisableTiming);
        cudaFuncSetAttribute(k_logits_bf, cudaFuncAttributeMaxDynamicSharedMemorySize, LOG_SMEM);
        cudaFuncSetAttribute(k_rr1t, cudaFuncAttributeMaxDynamicSharedMemorySize, RR1_SMEM);
    }

    k_init<<<2, 256>>>();
    cudaEventRecord(evS, 0);
    cudaStreamWaitEvent(s1, evS, 0);

    dim3 gpw(NPADB / 32, 16);
    k_packWb<<<gpw, 256, 0, s1>>>(w_cat);
    cudaEventRecord(evP, s1);
    dim3 gp1(16, RAWD / 32);
    k_packW1<<<gp1, 256, 0, s1>>>(w_o1);

    k_features<<<MM, 256>>>(x, w_suit, b_suit, gg_s, be_s,
                            w_rank, b_rank, gg_r, be_r,
                            w_h1, b_h1, w_h2, b_h2);
    cudaEventRecord(evF, 0);
    cudaStreamWaitEvent(s1, evF, 0);

    dim3 g41(4, 4, RRSPLIT);
    k_rr1t<<<g41, 256, RR1_SMEM, s1>>>();
    k_rr1red<<<MM, 256, 0, s1>>>(b_o1);
    k_rr2<<<MM, 256, 0, s1>>>(w_o2, b_o2);
    k_rr3<<<MM, 128, 0, s1>>>(w_o3, b_o3);
    cudaEventRecord(evJ, s1);

    cudaStreamWaitEvent(0, evP, 0);
    dim3 gl(NROWS / 128, NKT3);
    k_logits_bf<<<gl, 256, LOG_SMEM>>>(b_cat);
    k_argmax<<<NROWS, 128>>>(b_cat);

    cudaStreamWaitEvent(0, evJ, 0);
    k_final<<<MM, 32>>>(w_sc, b_sc, out);
}